// round 1
// baseline (speedup 1.0000x reference)
#include <cuda_runtime.h>
#include <cuda_bf16.h>

#define BB 2
#define TT 4096
#define CDIM 768
#define HH 12
#define DD 64
#define BT (BB*TT)   // 8192

// Scratch (allocation-free rule: __device__ globals)
__device__ float g_q[BT*CDIM];
__device__ float g_k[BT*CDIM];
__device__ float g_v[BT*CDIM];
__device__ float g_ctx[BT*CDIM];

// ---------------------------------------------------------------------------
// GEMM: Y[M,N] = X[M,K] * W[N,K]^T   with M=8192, N=K=768
// 64x64 tile, BK=16, 256 threads, 4x4 microtile.
// ---------------------------------------------------------------------------
__global__ void gemm_xwt_kernel(const float* __restrict__ X,
                                const float* __restrict__ W,
                                float* __restrict__ Y) {
    __shared__ float As[16][64];
    __shared__ float Bs[16][64];

    const int tid = threadIdx.x;
    const int tx = tid & 15;        // 0..15  (N micro)
    const int ty = tid >> 4;        // 0..15  (M micro)
    const int m0 = blockIdx.y * 64;
    const int n0 = blockIdx.x * 64;

    const int lr = tid >> 2;          // 0..63 tile row for loads
    const int lc = (tid & 3) << 2;    // 0,4,8,12 k-offset for loads

    float acc[4][4];
#pragma unroll
    for (int i = 0; i < 4; i++)
#pragma unroll
        for (int j = 0; j < 4; j++) acc[i][j] = 0.f;

    for (int k0 = 0; k0 < CDIM; k0 += 16) {
        float4 xa = *(const float4*)&X[(size_t)(m0 + lr) * CDIM + k0 + lc];
        float4 wb = *(const float4*)&W[(size_t)(n0 + lr) * CDIM + k0 + lc];
        __syncthreads();
        As[lc + 0][lr] = xa.x; As[lc + 1][lr] = xa.y;
        As[lc + 2][lr] = xa.z; As[lc + 3][lr] = xa.w;
        Bs[lc + 0][lr] = wb.x; Bs[lc + 1][lr] = wb.y;
        Bs[lc + 2][lr] = wb.z; Bs[lc + 3][lr] = wb.w;
        __syncthreads();
#pragma unroll
        for (int kk = 0; kk < 16; kk++) {
            float4 a = *(const float4*)&As[kk][ty * 4];
            float4 b = *(const float4*)&Bs[kk][tx * 4];
            acc[0][0] += a.x * b.x; acc[0][1] += a.x * b.y; acc[0][2] += a.x * b.z; acc[0][3] += a.x * b.w;
            acc[1][0] += a.y * b.x; acc[1][1] += a.y * b.y; acc[1][2] += a.y * b.z; acc[1][3] += a.y * b.w;
            acc[2][0] += a.z * b.x; acc[2][1] += a.z * b.y; acc[2][2] += a.z * b.z; acc[2][3] += a.z * b.w;
            acc[3][0] += a.w * b.x; acc[3][1] += a.w * b.y; acc[3][2] += a.w * b.z; acc[3][3] += a.w * b.w;
        }
    }

#pragma unroll
    for (int i = 0; i < 4; i++) {
        float4 o;
        o.x = acc[i][0]; o.y = acc[i][1]; o.z = acc[i][2]; o.w = acc[i][3];
        *(float4*)&Y[(size_t)(m0 + ty * 4 + i) * CDIM + n0 + tx * 4] = o;
    }
}

// ---------------------------------------------------------------------------
// Flash attention (causal), fp32, online softmax.
// Grid: (T/64, H, B). Block: 256 threads.
// Thread t: row r = t>>2 (query row in tile), quad = t&3.
//   quad owns key-cols c = quad*16..+15 in S, and d-cols d = quad*16..+15 in O.
// Smem rows padded to 68 floats (16B aligned, bank-spread).
// ---------------------------------------------------------------------------
#define ROWP 68
#define ATTN_SMEM (3 * 64 * ROWP * 4)

__global__ void attn_kernel(const float* __restrict__ q,
                            const float* __restrict__ k,
                            const float* __restrict__ v,
                            float* __restrict__ ctx) {
    extern __shared__ float sm[];
    float* Qs = sm;                 // 64 x 68
    float* Ks = sm + 64 * ROWP;     // 64 x 68
    float* Vs = sm + 2 * 64 * ROWP; // 64 x 68

    const int tid  = threadIdx.x;
    const int r    = tid >> 2;      // 0..63
    const int quad = tid & 3;       // 0..3
    const int lane = tid & 31;
    const int base = lane & ~3;

    const int qt = blockIdx.x;
    const int h  = blockIdx.y;
    const int b  = blockIdx.z;
    const int q0 = qt * 64;
    const float scale = 0.125f;     // 1/sqrt(64)

    // Load Q tile (pre-scaled)
    for (int e = tid; e < 64 * 64; e += 256) {
        int rr = e >> 6, cc = e & 63;
        Qs[rr * ROWP + cc] =
            q[(size_t)(b * TT + q0 + rr) * CDIM + h * DD + cc] * scale;
    }

    float4 acc4[4];
#pragma unroll
    for (int i = 0; i < 4; i++) acc4[i] = make_float4(0.f, 0.f, 0.f, 0.f);
    float m_i = -1e30f;
    float l_i = 0.f;

    for (int jt = 0; jt <= qt; jt++) {
        __syncthreads();
        // Load K,V tiles
        for (int e = tid; e < 64 * 64; e += 256) {
            int rr = e >> 6, cc = e & 63;
            size_t gidx = (size_t)(b * TT + jt * 64 + rr) * CDIM + h * DD + cc;
            Ks[rr * ROWP + cc] = k[gidx];
            Vs[rr * ROWP + cc] = v[gidx];
        }
        __syncthreads();

        // S = Q K^T for this thread's 16 key columns
        float s[16];
#pragma unroll
        for (int cc = 0; cc < 16; cc++) s[cc] = 0.f;

        const float4* Qr = (const float4*)&Qs[r * ROWP];
#pragma unroll
        for (int kk = 0; kk < 16; kk++) {
            float4 qv = Qr[kk];
#pragma unroll
            for (int cc = 0; cc < 16; cc++) {
                float4 kv = *(const float4*)&Ks[(quad * 16 + cc) * ROWP + kk * 4];
                s[cc] += qv.x * kv.x + qv.y * kv.y + qv.z * kv.z + qv.w * kv.w;
            }
        }

        // Causal mask on diagonal tile
        if (jt == qt) {
#pragma unroll
            for (int cc = 0; cc < 16; cc++) {
                int c = quad * 16 + cc;
                if (c > r) s[cc] = -1e30f;
            }
        }

        // Row max (16 local, then across quad)
        float mx = s[0];
#pragma unroll
        for (int cc = 1; cc < 16; cc++) mx = fmaxf(mx, s[cc]);
        mx = fmaxf(mx, __shfl_xor_sync(0xffffffffu, mx, 1));
        mx = fmaxf(mx, __shfl_xor_sync(0xffffffffu, mx, 2));
        float m_new = fmaxf(m_i, mx);

        // p = exp(s - m_new), partial row sum
        float p[16];
        float ls = 0.f;
#pragma unroll
        for (int cc = 0; cc < 16; cc++) {
            p[cc] = __expf(s[cc] - m_new);
            ls += p[cc];
        }
        ls += __shfl_xor_sync(0xffffffffu, ls, 1);
        ls += __shfl_xor_sync(0xffffffffu, ls, 2);

        float alpha = __expf(m_i - m_new);
        l_i = l_i * alpha + ls;
        m_i = m_new;
#pragma unroll
        for (int i = 0; i < 4; i++) {
            acc4[i].x *= alpha; acc4[i].y *= alpha;
            acc4[i].z *= alpha; acc4[i].w *= alpha;
        }

        // O += P @ V   (gather p across the 4 quad lanes via shuffle)
#pragma unroll
        for (int g = 0; g < 4; g++) {
#pragma unroll
            for (int j = 0; j < 16; j++) {
                float pc = __shfl_sync(0xffffffffu, p[j], base + g);
                const float4* Vr =
                    (const float4*)&Vs[(g * 16 + j) * ROWP + quad * 16];
#pragma unroll
                for (int dd = 0; dd < 4; dd++) {
                    float4 vv = Vr[dd];
                    acc4[dd].x += pc * vv.x;
                    acc4[dd].y += pc * vv.y;
                    acc4[dd].z += pc * vv.z;
                    acc4[dd].w += pc * vv.w;
                }
            }
        }
    }

    // Normalize and write ctx in (B,T,C) layout with head offset
    float inv = 1.f / l_i;
    size_t out_base = (size_t)(b * TT + q0 + r) * CDIM + h * DD + quad * 16;
#pragma unroll
    for (int dd = 0; dd < 4; dd++) {
        float4 o = acc4[dd];
        o.x *= inv; o.y *= inv; o.z *= inv; o.w *= inv;
        *(float4*)&ctx[out_base + dd * 4] = o;
    }
}

// ---------------------------------------------------------------------------
extern "C" void kernel_launch(void* const* d_in, const int* in_sizes, int n_in,
                              void* d_out, int out_size) {
    const float* x  = (const float*)d_in[0];
    const float* wq = (const float*)d_in[1];
    const float* wk = (const float*)d_in[2];
    const float* wv = (const float*)d_in[3];
    const float* wo = (const float*)d_in[4];
    float* out = (float*)d_out;

    float* q;   cudaGetSymbolAddress((void**)&q,   g_q);
    float* kk;  cudaGetSymbolAddress((void**)&kk,  g_k);
    float* v;   cudaGetSymbolAddress((void**)&v,   g_v);
    float* ctx; cudaGetSymbolAddress((void**)&ctx, g_ctx);

    cudaFuncSetAttribute(attn_kernel,
                         cudaFuncAttributeMaxDynamicSharedMemorySize, ATTN_SMEM);

    dim3 gg(CDIM / 64, BT / 64);
    gemm_xwt_kernel<<<gg, 256>>>(x, wq, q);
    gemm_xwt_kernel<<<gg, 256>>>(x, wk, kk);
    gemm_xwt_kernel<<<gg, 256>>>(x, wv, v);

    dim3 ga(TT / 64, HH, BB);
    attn_kernel<<<ga, 256, ATTN_SMEM>>>(q, kk, v, ctx);

    gemm_xwt_kernel<<<gg, 256>>>(ctx, wo, out);
}

// round 2
// speedup vs baseline: 9.2338x; 9.2338x over previous
#include <cuda_runtime.h>
#include <cuda_bf16.h>
#include <cstdint>

#define BB 2
#define TT 4096
#define CDIM 768
#define HH 12
#define DD 64
#define BT (BB*TT)   // 8192

// Scratch (allocation-free rule: __device__ globals)
__device__ float g_q[BT*CDIM];
__device__ float g_k[BT*CDIM];
__device__ float g_v[BT*CDIM];
__device__ float g_ctx[BT*CDIM];

// ---------------------------------------------------------------------------
// helpers: tf32 convert + m16n8k8 tf32 mma
// ---------------------------------------------------------------------------
__device__ __forceinline__ unsigned f2tf(float f) {
    unsigned u;
    asm("cvt.rna.tf32.f32 %0, %1;" : "=r"(u) : "f"(f));
    return u;
}

__device__ __forceinline__ void mma_tf32(float c[4], const unsigned a[4],
                                         const unsigned b[2]) {
    asm volatile(
        "mma.sync.aligned.m16n8k8.row.col.f32.tf32.tf32.f32 "
        "{%0,%1,%2,%3}, {%4,%5,%6,%7}, {%8,%9}, {%0,%1,%2,%3};\n"
        : "+f"(c[0]), "+f"(c[1]), "+f"(c[2]), "+f"(c[3])
        : "r"(a[0]), "r"(a[1]), "r"(a[2]), "r"(a[3]),
          "r"(b[0]), "r"(b[1]));
}

// ---------------------------------------------------------------------------
// GEMM: Y[M,N] = X[M,K] * W[N,K]^T,  M=8192, N=K=768
// Block 128x128, BK=32, 256 thr = 8 warps in 2(M) x 4(N), warp tile 64x32.
// smem rows padded to 36 floats -> fragment loads hit 32 distinct banks.
// ---------------------------------------------------------------------------
__global__ __launch_bounds__(256) void gemm_mma_kernel(
    const float* __restrict__ X, const float* __restrict__ W,
    float* __restrict__ Y) {
    __shared__ float As[128][36];
    __shared__ float Bs[128][36];

    const int tid  = threadIdx.x;
    const int warp = tid >> 5;
    const int lane = tid & 31;
    const int gid  = lane >> 2;   // 0..7
    const int tig  = lane & 3;    // 0..3
    const int wm   = warp >> 2;   // 0..1
    const int wn   = warp & 3;    // 0..3

    const int m0 = blockIdx.y * 128;
    const int n0 = blockIdx.x * 128;

    const int lrow = tid >> 3;         // 0..31
    const int lcol = (tid & 7) * 4;    // 0..28

    float c[4][4][4];
#pragma unroll
    for (int mt = 0; mt < 4; mt++)
#pragma unroll
        for (int nt = 0; nt < 4; nt++)
#pragma unroll
            for (int i = 0; i < 4; i++) c[mt][nt][i] = 0.f;

    for (int k0 = 0; k0 < CDIM; k0 += 32) {
        float4 xa[4], wb[4];
#pragma unroll
        for (int i = 0; i < 4; i++) {
            xa[i] = *(const float4*)&X[(size_t)(m0 + lrow + i * 32) * CDIM + k0 + lcol];
            wb[i] = *(const float4*)&W[(size_t)(n0 + lrow + i * 32) * CDIM + k0 + lcol];
        }
        __syncthreads();
#pragma unroll
        for (int i = 0; i < 4; i++) {
            *(float4*)&As[lrow + i * 32][lcol] = xa[i];
            *(float4*)&Bs[lrow + i * 32][lcol] = wb[i];
        }
        __syncthreads();

#pragma unroll
        for (int ks = 0; ks < 4; ks++) {
            const int kb = ks * 8;
            unsigned a[4][4], b[4][2];
#pragma unroll
            for (int mt = 0; mt < 4; mt++) {
                const int r = wm * 64 + mt * 16 + gid;
                a[mt][0] = f2tf(As[r][kb + tig]);
                a[mt][1] = f2tf(As[r + 8][kb + tig]);
                a[mt][2] = f2tf(As[r][kb + tig + 4]);
                a[mt][3] = f2tf(As[r + 8][kb + tig + 4]);
            }
#pragma unroll
            for (int nt = 0; nt < 4; nt++) {
                const int rn = wn * 32 + nt * 8 + gid;
                b[nt][0] = f2tf(Bs[rn][kb + tig]);
                b[nt][1] = f2tf(Bs[rn][kb + tig + 4]);
            }
#pragma unroll
            for (int mt = 0; mt < 4; mt++)
#pragma unroll
                for (int nt = 0; nt < 4; nt++)
                    mma_tf32(c[mt][nt], a[mt], b[nt]);
        }
    }

#pragma unroll
    for (int mt = 0; mt < 4; mt++) {
        const int r = m0 + wm * 64 + mt * 16 + gid;
#pragma unroll
        for (int nt = 0; nt < 4; nt++) {
            const int cn = n0 + wn * 32 + nt * 8 + 2 * tig;
            float2 o01 = make_float2(c[mt][nt][0], c[mt][nt][1]);
            float2 o23 = make_float2(c[mt][nt][2], c[mt][nt][3]);
            *(float2*)&Y[(size_t)r * CDIM + cn]       = o01;
            *(float2*)&Y[(size_t)(r + 8) * CDIM + cn] = o23;
        }
    }
}

// ---------------------------------------------------------------------------
// Flash attention (causal), tf32 mma, online softmax.
// Grid (T/64, H, B), block 128 thr = 4 warps; warp w owns query rows
// w*16..w*16+15 against all 64 key cols. P round-trips via per-warp smem.
// All smem tiles use 68-float rows (conflict-free fragment patterns).
// ---------------------------------------------------------------------------
#define AROW 68
#define ATTN_SMEM (4 * 64 * AROW * 4)

__global__ __launch_bounds__(128) void attn_mma_kernel(
    const float* __restrict__ q, const float* __restrict__ k,
    const float* __restrict__ v, float* __restrict__ ctx) {
    extern __shared__ float sm[];
    float* Qs = sm;
    float* Ks = sm + 64 * AROW;
    float* Vs = sm + 2 * 64 * AROW;
    float* Ps = sm + 3 * 64 * AROW;

    const int tid  = threadIdx.x;
    const int warp = tid >> 5;
    const int lane = tid & 31;
    const int gid  = lane >> 2;
    const int tig  = lane & 3;
    const int rw   = warp * 16 + gid;    // local row (this thread's row 0)

    const int qt = blockIdx.x;
    const int h  = blockIdx.y;
    const int b  = blockIdx.z;
    const int q0 = qt * 64;
    const float scale = 0.125f;

    // Load Q tile (scaled)
    for (int e = tid; e < 1024; e += 128) {
        int rr = e >> 4, cc = (e & 15) * 4;
        float4 val = *(const float4*)&q[(size_t)(b * TT + q0 + rr) * CDIM + h * DD + cc];
        val.x *= scale; val.y *= scale; val.z *= scale; val.w *= scale;
        *(float4*)&Qs[rr * AROW + cc] = val;
    }
    __syncthreads();

    // Q fragments (held for the whole q-tile)
    unsigned qa[8][4];
#pragma unroll
    for (int ks = 0; ks < 8; ks++) {
        qa[ks][0] = f2tf(Qs[rw * AROW + ks * 8 + tig]);
        qa[ks][1] = f2tf(Qs[(rw + 8) * AROW + ks * 8 + tig]);
        qa[ks][2] = f2tf(Qs[rw * AROW + ks * 8 + tig + 4]);
        qa[ks][3] = f2tf(Qs[(rw + 8) * AROW + ks * 8 + tig + 4]);
    }

    float o[8][4];
#pragma unroll
    for (int nt = 0; nt < 8; nt++)
#pragma unroll
        for (int i = 0; i < 4; i++) o[nt][i] = 0.f;
    float m0r = -1e30f, m1r = -1e30f, l0 = 0.f, l1 = 0.f;

    for (int jt = 0; jt <= qt; jt++) {
        __syncthreads();
        for (int e = tid; e < 1024; e += 128) {
            int rr = e >> 4, cc = (e & 15) * 4;
            size_t gbase = (size_t)(b * TT + jt * 64 + rr) * CDIM + h * DD + cc;
            *(float4*)&Ks[rr * AROW + cc] = *(const float4*)&k[gbase];
            *(float4*)&Vs[rr * AROW + cc] = *(const float4*)&v[gbase];
        }
        __syncthreads();

        // S = Q K^T  (16 x 64 per warp)
        float s[8][4];
#pragma unroll
        for (int nt = 0; nt < 8; nt++)
#pragma unroll
            for (int i = 0; i < 4; i++) s[nt][i] = 0.f;

#pragma unroll
        for (int ks = 0; ks < 8; ks++) {
            const int kb = ks * 8;
#pragma unroll
            for (int nt = 0; nt < 8; nt++) {
                unsigned bb[2];
                const int rn = nt * 8 + gid;
                bb[0] = f2tf(Ks[rn * AROW + kb + tig]);
                bb[1] = f2tf(Ks[rn * AROW + kb + tig + 4]);
                mma_tf32(s[nt], qa[ks], bb);
            }
        }

        // causal mask (diagonal tile only; off-diagonal tiles are fully valid)
        if (jt == qt) {
#pragma unroll
            for (int nt = 0; nt < 8; nt++) {
                const int cg = nt * 8 + 2 * tig;
                if (cg > rw)         s[nt][0] = -1e30f;
                if (cg + 1 > rw)     s[nt][1] = -1e30f;
                if (cg > rw + 8)     s[nt][2] = -1e30f;
                if (cg + 1 > rw + 8) s[nt][3] = -1e30f;
            }
        }

        // row maxima (two rows per thread)
        float mx0 = -1e30f, mx1 = -1e30f;
#pragma unroll
        for (int nt = 0; nt < 8; nt++) {
            mx0 = fmaxf(mx0, fmaxf(s[nt][0], s[nt][1]));
            mx1 = fmaxf(mx1, fmaxf(s[nt][2], s[nt][3]));
        }
        mx0 = fmaxf(mx0, __shfl_xor_sync(0xffffffffu, mx0, 1));
        mx0 = fmaxf(mx0, __shfl_xor_sync(0xffffffffu, mx0, 2));
        mx1 = fmaxf(mx1, __shfl_xor_sync(0xffffffffu, mx1, 1));
        mx1 = fmaxf(mx1, __shfl_xor_sync(0xffffffffu, mx1, 2));

        const float mn0 = fmaxf(m0r, mx0);
        const float mn1 = fmaxf(m1r, mx1);
        const float a0 = __expf(m0r - mn0);
        const float a1 = __expf(m1r - mn1);

        float ls0 = 0.f, ls1 = 0.f;
#pragma unroll
        for (int nt = 0; nt < 8; nt++) {
            s[nt][0] = __expf(s[nt][0] - mn0); ls0 += s[nt][0];
            s[nt][1] = __expf(s[nt][1] - mn0); ls0 += s[nt][1];
            s[nt][2] = __expf(s[nt][2] - mn1); ls1 += s[nt][2];
            s[nt][3] = __expf(s[nt][3] - mn1); ls1 += s[nt][3];
        }
        ls0 += __shfl_xor_sync(0xffffffffu, ls0, 1);
        ls0 += __shfl_xor_sync(0xffffffffu, ls0, 2);
        ls1 += __shfl_xor_sync(0xffffffffu, ls1, 1);
        ls1 += __shfl_xor_sync(0xffffffffu, ls1, 2);

        l0 = l0 * a0 + ls0; m0r = mn0;
        l1 = l1 * a1 + ls1; m1r = mn1;
#pragma unroll
        for (int nt = 0; nt < 8; nt++) {
            o[nt][0] *= a0; o[nt][1] *= a0;
            o[nt][2] *= a1; o[nt][3] *= a1;
        }

        // P -> smem (per-warp private rows: only __syncwarp needed)
#pragma unroll
        for (int nt = 0; nt < 8; nt++) {
            const int cc = nt * 8 + 2 * tig;
            *(float2*)&Ps[rw * AROW + cc]       = make_float2(s[nt][0], s[nt][1]);
            *(float2*)&Ps[(rw + 8) * AROW + cc] = make_float2(s[nt][2], s[nt][3]);
        }
        __syncwarp();

        // O += P V  (16 x 64 per warp)
#pragma unroll
        for (int kc = 0; kc < 8; kc++) {
            const int kb = kc * 8;
            unsigned pa[4];
            pa[0] = f2tf(Ps[rw * AROW + kb + tig]);
            pa[1] = f2tf(Ps[(rw + 8) * AROW + kb + tig]);
            pa[2] = f2tf(Ps[rw * AROW + kb + tig + 4]);
            pa[3] = f2tf(Ps[(rw + 8) * AROW + kb + tig + 4]);
#pragma unroll
            for (int nt = 0; nt < 8; nt++) {
                unsigned bb[2];
                bb[0] = f2tf(Vs[(kb + tig) * AROW + nt * 8 + gid]);
                bb[1] = f2tf(Vs[(kb + tig + 4) * AROW + nt * 8 + gid]);
                mma_tf32(o[nt], pa, bb);
            }
        }
    }

    // epilogue
    const float inv0 = 1.f / l0;
    const float inv1 = 1.f / l1;
    const size_t r0 = (size_t)(b * TT + q0 + rw) * CDIM + h * DD;
    const size_t r1 = (size_t)(b * TT + q0 + rw + 8) * CDIM + h * DD;
#pragma unroll
    for (int nt = 0; nt < 8; nt++) {
        const int cc = nt * 8 + 2 * tig;
        *(float2*)&ctx[r0 + cc] = make_float2(o[nt][0] * inv0, o[nt][1] * inv0);
        *(float2*)&ctx[r1 + cc] = make_float2(o[nt][2] * inv1, o[nt][3] * inv1);
    }
}

// ---------------------------------------------------------------------------
extern "C" void kernel_launch(void* const* d_in, const int* in_sizes, int n_in,
                              void* d_out, int out_size) {
    const float* x  = (const float*)d_in[0];
    const float* wq = (const float*)d_in[1];
    const float* wk = (const float*)d_in[2];
    const float* wv = (const float*)d_in[3];
    const float* wo = (const float*)d_in[4];
    float* out = (float*)d_out;

    float* q;   cudaGetSymbolAddress((void**)&q,   g_q);
    float* kk;  cudaGetSymbolAddress((void**)&kk,  g_k);
    float* v;   cudaGetSymbolAddress((void**)&v,   g_v);
    float* ctx; cudaGetSymbolAddress((void**)&ctx, g_ctx);

    cudaFuncSetAttribute(attn_mma_kernel,
                         cudaFuncAttributeMaxDynamicSharedMemorySize, ATTN_SMEM);

    dim3 gg(CDIM / 128, BT / 128);
    gemm_mma_kernel<<<gg, 256>>>(x, wq, q);
    gemm_mma_kernel<<<gg, 256>>>(x, wk, kk);
    gemm_mma_kernel<<<gg, 256>>>(x, wv, v);

    dim3 ga(TT / 64, HH, BB);
    attn_mma_kernel<<<ga, 128, ATTN_SMEM>>>(q, kk, v, ctx);

    gemm_mma_kernel<<<gg, 256>>>(ctx, wo, out);
}

// round 3
// speedup vs baseline: 13.1990x; 1.4294x over previous
#include <cuda_runtime.h>
#include <cuda_bf16.h>
#include <cstdint>

#define BB 2
#define TT 4096
#define CDIM 768
#define HH 12
#define DD 64
#define BT (BB*TT)   // 8192

// Scratch (allocation-free rule: __device__ globals)
// q/k/v hold tf32 bit patterns (written by projection GEMMs); ctx is f32.
__device__ float g_q[BT*CDIM];
__device__ float g_k[BT*CDIM];
__device__ float g_v[BT*CDIM];
__device__ float g_ctx[BT*CDIM];

// ---------------------------------------------------------------------------
// helpers
// ---------------------------------------------------------------------------
__device__ __forceinline__ unsigned f2tf(float f) {
    unsigned u;
    asm("cvt.rna.tf32.f32 %0, %1;" : "=r"(u) : "f"(f));
    return u;
}

__device__ __forceinline__ void mma_tf32(float c[4], const unsigned a[4],
                                         const unsigned b[2]) {
    asm volatile(
        "mma.sync.aligned.m16n8k8.row.col.f32.tf32.tf32.f32 "
        "{%0,%1,%2,%3}, {%4,%5,%6,%7}, {%8,%9}, {%0,%1,%2,%3};\n"
        : "+f"(c[0]), "+f"(c[1]), "+f"(c[2]), "+f"(c[3])
        : "r"(a[0]), "r"(a[1]), "r"(a[2]), "r"(a[3]),
          "r"(b[0]), "r"(b[1]));
}

__device__ __forceinline__ void cp_async16(uint32_t saddr, const void* gptr) {
    asm volatile("cp.async.cg.shared.global [%0], [%1], 16;"
                 :: "r"(saddr), "l"(gptr));
}
__device__ __forceinline__ void cp_async_commit() {
    asm volatile("cp.async.commit_group;");
}
__device__ __forceinline__ void cp_async_wait0() {
    asm volatile("cp.async.wait_group 0;");
}

// ---------------------------------------------------------------------------
// GEMM: Y[M,N] = X[M,K] * W[N,K]^T,  M=8192, N=K=768
// Block 128x128, BK=32, 256 thr = 8 warps (2M x 4N), warp tile 64x32.
// smem holds tf32 bits (converted at store); rows padded to 36 words.
// If TF32_OUT, epilogue writes tf32 bit patterns of (acc * out_scale).
// ---------------------------------------------------------------------------
template <bool TF32_OUT>
__global__ __launch_bounds__(256) void gemm_mma_kernel(
    const float* __restrict__ X, const float* __restrict__ W,
    float* __restrict__ Y, float out_scale) {
    __shared__ unsigned As[128][36];
    __shared__ unsigned Bs[128][36];

    const int tid  = threadIdx.x;
    const int warp = tid >> 5;
    const int lane = tid & 31;
    const int gid  = lane >> 2;   // 0..7
    const int tig  = lane & 3;    // 0..3
    const int wm   = warp >> 2;   // 0..1
    const int wn   = warp & 3;    // 0..3

    const int m0 = blockIdx.y * 128;
    const int n0 = blockIdx.x * 128;

    const int lrow = tid >> 3;         // 0..31
    const int lcol = (tid & 7) * 4;    // 0..28

    float c[4][4][4];
#pragma unroll
    for (int mt = 0; mt < 4; mt++)
#pragma unroll
        for (int nt = 0; nt < 4; nt++)
#pragma unroll
            for (int i = 0; i < 4; i++) c[mt][nt][i] = 0.f;

    for (int k0 = 0; k0 < CDIM; k0 += 32) {
        float4 xa[4], wb[4];
#pragma unroll
        for (int i = 0; i < 4; i++) {
            xa[i] = *(const float4*)&X[(size_t)(m0 + lrow + i * 32) * CDIM + k0 + lcol];
            wb[i] = *(const float4*)&W[(size_t)(n0 + lrow + i * 32) * CDIM + k0 + lcol];
        }
        __syncthreads();
#pragma unroll
        for (int i = 0; i < 4; i++) {
            uint4 xu, wu;
            xu.x = f2tf(xa[i].x); xu.y = f2tf(xa[i].y);
            xu.z = f2tf(xa[i].z); xu.w = f2tf(xa[i].w);
            wu.x = f2tf(wb[i].x); wu.y = f2tf(wb[i].y);
            wu.z = f2tf(wb[i].z); wu.w = f2tf(wb[i].w);
            *(uint4*)&As[lrow + i * 32][lcol] = xu;
            *(uint4*)&Bs[lrow + i * 32][lcol] = wu;
        }
        __syncthreads();

#pragma unroll
        for (int ks = 0; ks < 4; ks++) {
            const int kb = ks * 8;
            unsigned a[4][4], b[4][2];
#pragma unroll
            for (int mt = 0; mt < 4; mt++) {
                const int r = wm * 64 + mt * 16 + gid;
                a[mt][0] = As[r][kb + tig];
                a[mt][1] = As[r + 8][kb + tig];
                a[mt][2] = As[r][kb + tig + 4];
                a[mt][3] = As[r + 8][kb + tig + 4];
            }
#pragma unroll
            for (int nt = 0; nt < 4; nt++) {
                const int rn = wn * 32 + nt * 8 + gid;
                b[nt][0] = Bs[rn][kb + tig];
                b[nt][1] = Bs[rn][kb + tig + 4];
            }
#pragma unroll
            for (int mt = 0; mt < 4; mt++)
#pragma unroll
                for (int nt = 0; nt < 4; nt++)
                    mma_tf32(c[mt][nt], a[mt], b[nt]);
        }
    }

#pragma unroll
    for (int mt = 0; mt < 4; mt++) {
        const int r = m0 + wm * 64 + mt * 16 + gid;
#pragma unroll
        for (int nt = 0; nt < 4; nt++) {
            const int cn = n0 + wn * 32 + nt * 8 + 2 * tig;
            if (TF32_OUT) {
                uint2 o01 = make_uint2(f2tf(c[mt][nt][0] * out_scale),
                                       f2tf(c[mt][nt][1] * out_scale));
                uint2 o23 = make_uint2(f2tf(c[mt][nt][2] * out_scale),
                                       f2tf(c[mt][nt][3] * out_scale));
                *(uint2*)&Y[(size_t)r * CDIM + cn]       = o01;
                *(uint2*)&Y[(size_t)(r + 8) * CDIM + cn] = o23;
            } else {
                *(float2*)&Y[(size_t)r * CDIM + cn] =
                    make_float2(c[mt][nt][0], c[mt][nt][1]);
                *(float2*)&Y[(size_t)(r + 8) * CDIM + cn] =
                    make_float2(c[mt][nt][2], c[mt][nt][3]);
            }
        }
    }
}

// ---------------------------------------------------------------------------
// Flash attention (causal), tf32 mma, online softmax.
// q/k/v buffers hold tf32 bits (Q pre-scaled). Mainloop has zero cvts on
// Q/K/V; K/V tiles come in via cp.async. P converts to tf32 at smem store.
// Grid (T/64, H, B) with qt reversed for tail-balance. 128 thr = 4 warps.
// Pads: Q/K/P rows 68 words, V rows 72 words (all fragment patterns hit
// 32 distinct banks).
// ---------------------------------------------------------------------------
#define KROW 68
#define VROW 72
#define ATTN_SMEM ((3 * 64 * KROW + 64 * VROW) * 4)

__global__ __launch_bounds__(128) void attn_mma_kernel(
    const float* __restrict__ q, const float* __restrict__ k,
    const float* __restrict__ v, float* __restrict__ ctx) {
    extern __shared__ unsigned sm[];
    unsigned* Qs = sm;
    unsigned* Ks = sm + 64 * KROW;
    unsigned* Ps = sm + 2 * 64 * KROW;
    unsigned* Vs = sm + 3 * 64 * KROW;

    const int tid  = threadIdx.x;
    const int warp = tid >> 5;
    const int lane = tid & 31;
    const int gid  = lane >> 2;
    const int tig  = lane & 3;
    const int rw   = warp * 16 + gid;    // this thread's first local row

    const int qt = gridDim.x - 1 - blockIdx.x;   // long blocks first
    const int h  = blockIdx.y;
    const int b  = blockIdx.z;
    const int q0 = qt * 64;

    const uint32_t qs_base = (uint32_t)__cvta_generic_to_shared(Qs);
    const uint32_t ks_base = (uint32_t)__cvta_generic_to_shared(Ks);
    const uint32_t vs_base = (uint32_t)__cvta_generic_to_shared(Vs);

    // Q tile: raw copy (already scaled tf32 bits)
    for (int e = tid; e < 1024; e += 128) {
        int rr = e >> 4, c4 = (e & 15) * 4;
        cp_async16(qs_base + (rr * KROW + c4) * 4,
                   &q[(size_t)(b * TT + q0 + rr) * CDIM + h * DD + c4]);
    }
    cp_async_commit();
    cp_async_wait0();
    __syncthreads();

    // Q fragments (held for the whole q-tile)
    unsigned qa[8][4];
#pragma unroll
    for (int ks = 0; ks < 8; ks++) {
        qa[ks][0] = Qs[rw * KROW + ks * 8 + tig];
        qa[ks][1] = Qs[(rw + 8) * KROW + ks * 8 + tig];
        qa[ks][2] = Qs[rw * KROW + ks * 8 + tig + 4];
        qa[ks][3] = Qs[(rw + 8) * KROW + ks * 8 + tig + 4];
    }

    float o[8][4];
#pragma unroll
    for (int nt = 0; nt < 8; nt++)
#pragma unroll
        for (int i = 0; i < 4; i++) o[nt][i] = 0.f;
    float m0r = -1e30f, m1r = -1e30f, l0 = 0.f, l1 = 0.f;

    for (int jt = 0; jt <= qt; jt++) {
        __syncthreads();   // prior compute done before smem overwrite
        for (int e = tid; e < 1024; e += 128) {
            int rr = e >> 4, c4 = (e & 15) * 4;
            size_t gbase = (size_t)(b * TT + jt * 64 + rr) * CDIM + h * DD + c4;
            cp_async16(ks_base + (rr * KROW + c4) * 4, &k[gbase]);
            cp_async16(vs_base + (rr * VROW + c4) * 4, &v[gbase]);
        }
        cp_async_commit();
        cp_async_wait0();
        __syncthreads();

        // S = Q K^T  (16 x 64 per warp)
        float s[8][4];
#pragma unroll
        for (int nt = 0; nt < 8; nt++)
#pragma unroll
            for (int i = 0; i < 4; i++) s[nt][i] = 0.f;

#pragma unroll
        for (int ks = 0; ks < 8; ks++) {
            const int kb = ks * 8;
#pragma unroll
            for (int nt = 0; nt < 8; nt++) {
                unsigned bb[2];
                const int rn = nt * 8 + gid;
                bb[0] = Ks[rn * KROW + kb + tig];
                bb[1] = Ks[rn * KROW + kb + tig + 4];
                mma_tf32(s[nt], qa[ks], bb);
            }
        }

        // causal mask (diagonal tile only)
        if (jt == qt) {
#pragma unroll
            for (int nt = 0; nt < 8; nt++) {
                const int cg = nt * 8 + 2 * tig;
                if (cg > rw)         s[nt][0] = -1e30f;
                if (cg + 1 > rw)     s[nt][1] = -1e30f;
                if (cg > rw + 8)     s[nt][2] = -1e30f;
                if (cg + 1 > rw + 8) s[nt][3] = -1e30f;
            }
        }

        // row maxima (two rows per thread)
        float mx0 = -1e30f, mx1 = -1e30f;
#pragma unroll
        for (int nt = 0; nt < 8; nt++) {
            mx0 = fmaxf(mx0, fmaxf(s[nt][0], s[nt][1]));
            mx1 = fmaxf(mx1, fmaxf(s[nt][2], s[nt][3]));
        }
        mx0 = fmaxf(mx0, __shfl_xor_sync(0xffffffffu, mx0, 1));
        mx0 = fmaxf(mx0, __shfl_xor_sync(0xffffffffu, mx0, 2));
        mx1 = fmaxf(mx1, __shfl_xor_sync(0xffffffffu, mx1, 1));
        mx1 = fmaxf(mx1, __shfl_xor_sync(0xffffffffu, mx1, 2));

        const float mn0 = fmaxf(m0r, mx0);
        const float mn1 = fmaxf(m1r, mx1);
        const float a0 = __expf(m0r - mn0);
        const float a1 = __expf(m1r - mn1);

        float ls0 = 0.f, ls1 = 0.f;
#pragma unroll
        for (int nt = 0; nt < 8; nt++) {
            s[nt][0] = __expf(s[nt][0] - mn0); ls0 += s[nt][0];
            s[nt][1] = __expf(s[nt][1] - mn0); ls0 += s[nt][1];
            s[nt][2] = __expf(s[nt][2] - mn1); ls1 += s[nt][2];
            s[nt][3] = __expf(s[nt][3] - mn1); ls1 += s[nt][3];
        }
        ls0 += __shfl_xor_sync(0xffffffffu, ls0, 1);
        ls0 += __shfl_xor_sync(0xffffffffu, ls0, 2);
        ls1 += __shfl_xor_sync(0xffffffffu, ls1, 1);
        ls1 += __shfl_xor_sync(0xffffffffu, ls1, 2);

        l0 = l0 * a0 + ls0; m0r = mn0;
        l1 = l1 * a1 + ls1; m1r = mn1;
#pragma unroll
        for (int nt = 0; nt < 8; nt++) {
            o[nt][0] *= a0; o[nt][1] *= a0;
            o[nt][2] *= a1; o[nt][3] *= a1;
        }

        // P -> smem as tf32 (per-warp private rows: only __syncwarp)
#pragma unroll
        for (int nt = 0; nt < 8; nt++) {
            const int cc = nt * 8 + 2 * tig;
            *(uint2*)&Ps[rw * KROW + cc] =
                make_uint2(f2tf(s[nt][0]), f2tf(s[nt][1]));
            *(uint2*)&Ps[(rw + 8) * KROW + cc] =
                make_uint2(f2tf(s[nt][2]), f2tf(s[nt][3]));
        }
        __syncwarp();

        // O += P V  (16 x 64 per warp)
#pragma unroll
        for (int kc = 0; kc < 8; kc++) {
            const int kb = kc * 8;
            unsigned pa[4];
            pa[0] = Ps[rw * KROW + kb + tig];
            pa[1] = Ps[(rw + 8) * KROW + kb + tig];
            pa[2] = Ps[rw * KROW + kb + tig + 4];
            pa[3] = Ps[(rw + 8) * KROW + kb + tig + 4];
#pragma unroll
            for (int nt = 0; nt < 8; nt++) {
                unsigned bb[2];
                bb[0] = Vs[(kb + tig) * VROW + nt * 8 + gid];
                bb[1] = Vs[(kb + tig + 4) * VROW + nt * 8 + gid];
                mma_tf32(o[nt], pa, bb);
            }
        }
    }

    // epilogue (f32 out)
    const float inv0 = 1.f / l0;
    const float inv1 = 1.f / l1;
    const size_t r0 = (size_t)(b * TT + q0 + rw) * CDIM + h * DD;
    const size_t r1 = (size_t)(b * TT + q0 + rw + 8) * CDIM + h * DD;
#pragma unroll
    for (int nt = 0; nt < 8; nt++) {
        const int cc = nt * 8 + 2 * tig;
        *(float2*)&ctx[r0 + cc] = make_float2(o[nt][0] * inv0, o[nt][1] * inv0);
        *(float2*)&ctx[r1 + cc] = make_float2(o[nt][2] * inv1, o[nt][3] * inv1);
    }
}

// ---------------------------------------------------------------------------
extern "C" void kernel_launch(void* const* d_in, const int* in_sizes, int n_in,
                              void* d_out, int out_size) {
    const float* x  = (const float*)d_in[0];
    const float* wq = (const float*)d_in[1];
    const float* wk = (const float*)d_in[2];
    const float* wv = (const float*)d_in[3];
    const float* wo = (const float*)d_in[4];
    float* out = (float*)d_out;

    float* q;   cudaGetSymbolAddress((void**)&q,   g_q);
    float* kk;  cudaGetSymbolAddress((void**)&kk,  g_k);
    float* v;   cudaGetSymbolAddress((void**)&v,   g_v);
    float* ctx; cudaGetSymbolAddress((void**)&ctx, g_ctx);

    cudaFuncSetAttribute(attn_mma_kernel,
                         cudaFuncAttributeMaxDynamicSharedMemorySize, ATTN_SMEM);

    dim3 gg(CDIM / 128, BT / 128);
    // Q pre-scaled by 1/sqrt(D), written as tf32 bits
    gemm_mma_kernel<true><<<gg, 256>>>(x, wq, q, 0.125f);
    gemm_mma_kernel<true><<<gg, 256>>>(x, wk, kk, 1.0f);
    gemm_mma_kernel<true><<<gg, 256>>>(x, wv, v, 1.0f);

    dim3 ga(TT / 64, HH, BB);
    attn_mma_kernel<<<ga, 128, ATTN_SMEM>>>(q, kk, v, ctx);

    gemm_mma_kernel<false><<<gg, 256>>>(ctx, wo, out, 1.0f);
}